// round 1
// baseline (speedup 1.0000x reference)
#include <cuda_runtime.h>

// Problem constants (fixed by the dataset generator)
#define L35   35            // number of (lx,ly,lz) monomials, zmax=4
#define NRAD  16
#define RADC  5             // radial channels: 4 zeta + 1 two-body
#define NZ    4             // zeta values 1..4 -> radial channels 0..3
#define NL    2             // lambda weights
#define KT    5             // k (angular) values per thread
#define KG    7             // k groups: KG*KT = 35
#define ACTIVE (NRAD*KG)    // 112 worker threads
#define BLOCK 128
#define TEDGE 8             // edges per shared tile
#define NOUT  (NRAD*(1 + NL*NZ))  // 144 output columns per atom

__global__ __launch_bounds__(BLOCK)
void mbp_atom_kernel(const float* __restrict__ rij,     // [E,3] unit vectors
                     const float* __restrict__ radial,  // [E,NRAD,RADC]
                     const float* __restrict__ lamw,    // [NL]
                     const float* __restrict__ fn,      // [L35]
                     const int*   __restrict__ fidx,    // [E] sorted atom ids
                     const int*   __restrict__ lxlylz,  // [L35,3]
                     const int*   __restrict__ lsum,    // [L35]
                     float* __restrict__ out,           // [nat, NOUT]
                     int E)
{
    __shared__ __align__(16) float s_rad[TEDGE][NRAD*RADC]; // [8][80]
    __shared__ float s_g [TEDGE][L35];
    __shared__ float s_pw[TEDGE][3][5];     // powers v^0..v^4
    __shared__ float s_fn[L35];
    __shared__ int   s_lx[L35], s_ly[L35], s_lz[L35];
    __shared__ float s_lam[NL][L35];
    __shared__ float s_sq[NZ][NRAD][L35];   // acc^2 staging for epilogue
    __shared__ int   s_se[2];

    const int tid = threadIdx.x;
    const int a   = blockIdx.x;

    // ---- one-time block setup (no inter-phase dependency -> single sync) ----
    if (tid < L35) {
        s_fn[tid] = fn[tid];
        s_lx[tid] = lxlylz[tid*3+0];
        s_ly[tid] = lxlylz[tid*3+1];
        s_lz[tid] = lxlylz[tid*3+2];
    }
    if (tid < NL*L35) {
        int l = tid / L35, k = tid - l*L35;
        float b = lamw[l];
        int   s = lsum[k];
        float p = 1.f;                 // exact integer power (b may be < 0)
        for (int i = 0; i < s; i++) p *= b;
        s_lam[l][k] = p;
    }
    if (tid < 2) {                     // lower_bound(a), lower_bound(a+1)
        int target = a + tid;
        int lo = 0, hi = E;
        while (lo < hi) {
            int mid = (lo + hi) >> 1;
            if (fidx[mid] < target) lo = mid + 1; else hi = mid;
        }
        s_se[tid] = lo;
    }
    __syncthreads();
    const int start = s_se[0], end = s_se[1];

    // ---- per-thread accumulators: (j, k0..k0+4) x 4 zeta channels ----
    float acc0[KT] = {0.f,0.f,0.f,0.f,0.f};
    float acc1[KT] = {0.f,0.f,0.f,0.f,0.f};
    float acc2[KT] = {0.f,0.f,0.f,0.f,0.f};
    float acc3[KT] = {0.f,0.f,0.f,0.f,0.f};
    float accR = 0.f;                  // two-body radial (channel 4), kg==0 only
    const int j  = tid / KG;           // 0..15 (only meaningful for tid<ACTIVE)
    const int kg = tid % KG;
    const int k0 = kg * KT;

    const float4* rad4 = (const float4*)radial;  // 80 floats = 20 float4 per edge row

    for (int base = start; base < end; base += TEDGE) {
        const int cnt = min(TEDGE, end - base);
        __syncthreads();  // WAR: previous FMA phase done reading tile buffers

        // load radial rows (vectorized) + power tables
        for (int i = tid; i < cnt*20; i += BLOCK) {
            int t = i / 20, q = i - t*20;
            ((float4*)s_rad[t])[q] = rad4[(size_t)(base + t)*20 + q];
        }
        for (int i = tid; i < cnt*3; i += BLOCK) {
            int t = i / 3, c = i - t*3;
            float v  = rij[(size_t)(base + t)*3 + c];
            float v2 = v*v;
            s_pw[t][c][0] = 1.f;
            s_pw[t][c][1] = v;
            s_pw[t][c][2] = v2;
            s_pw[t][c][3] = v2*v;
            s_pw[t][c][4] = v2*v2;
        }
        __syncthreads();

        // angular monomials g[t][k] = fn[k] * x^lx * y^ly * z^lz
        for (int i = tid; i < cnt*L35; i += BLOCK) {
            int t = i / L35, k = i - t*L35;
            s_g[t][k] = s_fn[k] * s_pw[t][0][s_lx[k]]
                                * s_pw[t][1][s_ly[k]]
                                * s_pw[t][2][s_lz[k]];
        }
        __syncthreads();

        // main FMA phase: acc[r][j][k] += radial[e,j,r] * g[e,k]
        if (tid < ACTIVE) {
            #pragma unroll
            for (int t = 0; t < TEDGE; t++) {
                if (t >= cnt) break;
                const float* rp = &s_rad[t][j*RADC];
                float r0 = rp[0], r1 = rp[1], r2 = rp[2], r3 = rp[3];
                if (kg == 0) accR += rp[4];
                const float* gp = &s_g[t][k0];
                #pragma unroll
                for (int q = 0; q < KT; q++) {
                    float g = gp[q];
                    acc0[q] = fmaf(r0, g, acc0[q]);
                    acc1[q] = fmaf(r1, g, acc1[q]);
                    acc2[q] = fmaf(r2, g, acc2[q]);
                    acc3[q] = fmaf(r3, g, acc3[q]);
                }
            }
        }
    }

    // ---- epilogue: squares -> lambda contraction -> output ----
    __syncthreads();
    if (tid < ACTIVE) {
        #pragma unroll
        for (int q = 0; q < KT; q++) {
            s_sq[0][j][k0+q] = acc0[q]*acc0[q];
            s_sq[1][j][k0+q] = acc1[q]*acc1[q];
            s_sq[2][j][k0+q] = acc2[q]*acc2[q];
            s_sq[3][j][k0+q] = acc3[q]*acc3[q];
        }
        if (kg == 0) out[(size_t)a*NOUT + j] = accR;
    }
    __syncthreads();
    {
        // 128 threads -> 128 outputs: (j2, r, l)
        int j2 = tid >> 3;          // 0..15
        int r  = (tid >> 1) & 3;    // 0..3  (zeta index, z=r+1)
        int l  = tid & 1;           // 0..1
        float sum = 0.f;
        #pragma unroll
        for (int k = 0; k < L35; k++)
            sum = fmaf(s_sq[r][j2][k], s_lam[l][k], sum);
        // scale 2^(1-z) = 2^(-r)
        float scale = (r == 0) ? 1.f : (r == 1 ? 0.5f : (r == 2 ? 0.25f : 0.125f));
        out[(size_t)a*NOUT + NRAD + r*(NRAD*NL) + j2*NL + l] = sum * scale;
    }
}

extern "C" void kernel_launch(void* const* d_in, const int* in_sizes, int n_in,
                              void* d_out, int out_size)
{
    const float* rij    = (const float*)d_in[0];   // [E,3]
    const float* radial = (const float*)d_in[1];   // [E,16,5]
    const float* lamw   = (const float*)d_in[2];   // [2]
    const float* fn     = (const float*)d_in[3];   // [35]
    const int*   fidx   = (const int*)  d_in[4];   // [E]
    const int*   lxlylz = (const int*)  d_in[5];   // [35,3]
    const int*   lsum   = (const int*)  d_in[6];   // [35]

    const int E   = in_sizes[0] / 3;
    const int nat = out_size / NOUT;

    mbp_atom_kernel<<<nat, BLOCK>>>(rij, radial, lamw, fn, fidx, lxlylz, lsum,
                                    (float*)d_out, E);
}